// round 4
// baseline (speedup 1.0000x reference)
#include <cuda_runtime.h>
#include <cuda_bf16.h>

// Scratch for pooled diff: [32, 128, 128] floats = 2 MB (static, no allocs).
__device__ float g_diff[32 * 128 * 128];

// Grid-barrier arrival counter. Monotonically increasing across graph
// replays; each launch adds exactly GRID, so round targets stay aligned
// and no reset is ever needed (deterministic, graph-safe).
__device__ unsigned g_arrive = 0;

#define GRIDN 148
#define NWARPS (GRIDN * 32)          // 4736 warps total
#define NTILES (32 * 128 * 4)        // 16384 warp-tiles (b, py, warp-col)
#define NSEG   (32 * 128 * 32)       // 131072 4-wide TV segments

__global__ __launch_bounds__(1024, 1) void fused_spa_kernel(
    const float* __restrict__ org, const float* __restrict__ enh,
    float* __restrict__ out)
{
    const int lane = threadIdx.x & 31;
    const int gw   = (blockIdx.x << 5) + (threadIdx.x >> 5);  // global warp id

    if (blockIdx.x == 0 && threadIdx.x == 0) out[0] = 0.f;

    // ---- Phase 1: pooled channel-mean diff -> g_diff ----
    // warp-tile = one (batch, pooled-row, 32-col group). Lane handles one
    // pooled col: 3ch x 4rows x float4 from each tensor (48 LDG.128, coalesced).
    for (int wt = gw; wt < NTILES; wt += NWARPS) {
        const int b   = wt >> 9;            // 512 warp-tiles per image
        const int rem = wt & 511;
        const int py  = rem >> 2;
        const int pc  = ((rem & 3) << 5) + lane;

        float s = 0.f;
#pragma unroll
        for (int c = 0; c < 3; ++c) {
#pragma unroll
            for (int dy = 0; dy < 4; ++dy) {
                const size_t off = (((size_t)(b * 3 + c) * 512) + (size_t)(py * 4 + dy)) * 512
                                   + (size_t)(4 * pc);
                const float4 o = *reinterpret_cast<const float4*>(org + off);
                const float4 e = *reinterpret_cast<const float4*>(enh + off);
                s += (o.x - e.x) + (o.y - e.y) + (o.z - e.z) + (o.w - e.w);
            }
        }
        g_diff[(b << 14) + (py << 7) + pc] = s * (1.0f / 48.0f);
    }

    // ---- Grid barrier (all GRIDN blocks resident by construction) ----
    __syncthreads();                 // all warps in block finished phase 1
    if (threadIdx.x == 0) {
        __threadfence();             // publish g_diff (and out=0)
        const unsigned ticket = atomicAdd(&g_arrive, 1u);
        const unsigned target = (ticket / GRIDN + 1u) * GRIDN;
        volatile unsigned* va = &g_arrive;
        while (*va < target) { }
        __threadfence();             // acquire: see all blocks' g_diff
    }
    __syncthreads();

    // ---- Phase 2: 4-direction shift-diff^2 + full reduction ----
    // Each thread owns one 4-wide row segment (float4 center/up/down + halos).
    const int tid = blockIdx.x * 1024 + threadIdx.x;   // 0 .. 151551
    float v = 0.f;
    if (tid < NSEG) {
        const int b  = tid >> 12;         // 4096 segments per image
        const int r  = tid & 4095;
        const int y  = r >> 5;            // row 0..127
        const int sx = (r & 31) << 2;     // segment start col

        const float* __restrict__ img = g_diff + ((size_t)b << 14);
        const int p = (y << 7) + sx;

        const float4 c = *reinterpret_cast<const float4*>(img + p);
        const float  l  = (sx > 0)   ? img[p - 1] : 0.f;
        const float  rr = (sx < 124) ? img[p + 4] : 0.f;

        float4 u, dn;
        if (y > 0)   u  = *reinterpret_cast<const float4*>(img + p - 128);
        else         u  = make_float4(0.f, 0.f, 0.f, 0.f);
        if (y < 127) dn = *reinterpret_cast<const float4*>(img + p + 128);
        else         dn = make_float4(0.f, 0.f, 0.f, 0.f);

        float a;
        a = c.x - l;    v += a * a;
        a = c.x - c.y;  v += a * a;
        a = c.x - u.x;  v += a * a;
        a = c.x - dn.x; v += a * a;

        a = c.y - c.x;  v += a * a;
        a = c.y - c.z;  v += a * a;
        a = c.y - u.y;  v += a * a;
        a = c.y - dn.y; v += a * a;

        a = c.z - c.y;  v += a * a;
        a = c.z - c.w;  v += a * a;
        a = c.z - u.z;  v += a * a;
        a = c.z - dn.z; v += a * a;

        a = c.w - c.z;  v += a * a;
        a = c.w - rr;   v += a * a;
        a = c.w - u.w;  v += a * a;
        a = c.w - dn.w; v += a * a;
    }

    // warp reduce
#pragma unroll
    for (int o = 16; o > 0; o >>= 1)
        v += __shfl_xor_sync(0xFFFFFFFFu, v, o);

    __shared__ float ws[32];
    if (lane == 0) ws[threadIdx.x >> 5] = v;
    __syncthreads();

    if (threadIdx.x < 32) {
        float vv = ws[threadIdx.x];
#pragma unroll
        for (int o = 16; o > 0; o >>= 1)
            vv += __shfl_xor_sync(0xFFFFFFFFu, vv, o);
        if (threadIdx.x == 0)
            atomicAdd(out, vv * (1.0f / (32.0f * 128.0f * 128.0f)));
    }
}

extern "C" void kernel_launch(void* const* d_in, const int* in_sizes, int n_in,
                              void* d_out, int out_size)
{
    const float* org = (const float*)d_in[0];
    const float* enh = (const float*)d_in[1];
    float* out = (float*)d_out;

    fused_spa_kernel<<<GRIDN, 1024>>>(org, enh, out);
}